// round 16
// baseline (speedup 1.0000x reference)
#include <cuda_runtime.h>
#include <cuda_bf16.h>
#include <cstdint>

// VectorQuantizer R15: SINGLE bf16 mma sweep. Candidates flagged against the
// lane-local running threshold (provable superset of the final-threshold set)
// are pushed as (quantized score, k) into per-thread smem slots; after the
// final per-row threshold is known they are re-filtered and only true
// candidates (~1.3/row) get the exact fp32 rescore (R2 byte-identical).
// Code dimension split across warp pairs, B frags via LDG (L1-resident).

#define NUM_CODES 1024
#define DIM       64
#define HW        1024
#define N_VEC     32768
#define N_TOTAL   2097152
#define TPB       256          // 8 warps = 4 row-groups x 2 code-halves
#define VPB       64           // vectors per CTA
#define NBLOCKS   512
#define EPS2      1.6e-3f      // >= 2*(bf16 err 6.8e-4 + cn_max 6.1e-5)
#define INF       3.402823466e38f
#define ZPAD      65           // z row stride (f32): conflict-free LDS
#define NSLOT     16           // candidate slots per row-stream

// smem layout (bytes)
#define OFF_Z     0            // 64 rows x 65 f32 = 16640
#define OFF_CN    16640        // 1024 f32         = 4096
#define OFF_RM    20736        // 128 f32 (row x half row-min)
#define OFF_BST   21248        // 128 f32 (row x half best)
#define OFF_BSK   21760        // 128 i32 (row x half best k)
#define OFF_RED   22272        // 256 f32 = 1024
#define OFF_SLOT  23296        // 32 x 256 u32 = 32768
#define SMEM_TOTAL 56064

__device__ float        g_cnorm[NUM_CODES];
__device__ float        g_partial[NBLOCKS];
__device__ __align__(16) uint4 g_bfrag[NUM_CODES * 8];  // 128 KB bf16 B frags
__device__ unsigned int g_done;

__device__ __forceinline__ uint32_t pk_bf2(float lo, float hi) {
    uint32_t u;
    asm("cvt.rn.bf16x2.f32 %0, %1, %2;" : "=r"(u) : "f"(hi), "f"(lo));
    return u;
}
__device__ __forceinline__ void mma_bf16(float* d, const uint32_t* a,
                                         uint32_t b0, uint32_t b1) {
    asm("mma.sync.aligned.m16n8k16.row.col.f32.bf16.bf16.f32 "
        "{%0,%1,%2,%3}, {%4,%5,%6,%7}, {%8,%9}, {%0,%1,%2,%3};"
        : "+f"(d[0]), "+f"(d[1]), "+f"(d[2]), "+f"(d[3])
        : "r"(a[0]), "r"(a[1]), "r"(a[2]), "r"(a[3]), "r"(b0), "r"(b1));
}

// monotone u16 fixed-point of a proxy score (resolution 3e-5 << EPS2)
__device__ __forceinline__ uint32_t pack_cand(float s, int k) {
    float q = fmaf(s, 32767.0f, 32768.0f);
    q = fminf(fmaxf(q, 0.0f), 65535.0f);
    return ((uint32_t)q << 16) | (uint32_t)k;
}
__device__ __forceinline__ uint32_t quant_th(float th) {
    float q = fmaf(th, 32767.0f, 32768.0f);
    q = fminf(fmaxf(q, 0.0f), 65535.0f);
    return (uint32_t)q + 2;   // conservative slack vs rounding
}

// exact fp32 score, byte-identical sequence to the round-2 passing kernel
__device__ __forceinline__ float exact_score(const float* __restrict__ cb, int k,
                                             const float* zrow, float zn, float cn) {
    const float4* row = (const float4*)(cb + (size_t)k * DIM);
    float d = 0.0f;
#pragma unroll 4
    for (int i = 0; i < 16; i++) {
        float4 a = row[i];
        d = fmaf(a.x, zrow[4 * i + 0], d);
        d = fmaf(a.y, zrow[4 * i + 1], d);
        d = fmaf(a.z, zrow[4 * i + 2], d);
        d = fmaf(a.w, zrow[4 * i + 3], d);
    }
    return __fadd_rn(__fsub_rn(zn, __fmul_rn(2.0f, d)), cn);
}

// ---------------------------------------------------------------------------
// Prep: warp per code — cn + 8 paired-kstep uint4 B-fragment slots
// (layout validated R11-R13).
// ---------------------------------------------------------------------------
__global__ void prep_kernel(const float* __restrict__ cb) {
    int k = (blockIdx.x * blockDim.x + threadIdx.x) >> 5;
    int l = threadIdx.x & 31;
    if (k >= NUM_CODES) return;
    const float* row = cb + (size_t)k * DIM;
    float2 v = *(const float2*)(row + 2 * l);
    float cn = fmaf(v.x, v.x, v.y * v.y);
#pragma unroll
    for (int off = 16; off; off >>= 1)
        cn += __shfl_xor_sync(0xFFFFFFFFu, cn, off);
    if (l == 0) g_cnorm[k] = cn;

    if (l < 8) {
        int h = l >> 2, t = l & 3;
        int g = k >> 3, n = k & 7;
        int kkA = 2 * h, kkB = 2 * h + 1;
        uint4 val;
        val.x = pk_bf2(row[16 * kkA + 2 * t],     row[16 * kkA + 2 * t + 1]);
        val.y = pk_bf2(row[16 * kkA + 2 * t + 8], row[16 * kkA + 2 * t + 9]);
        val.z = pk_bf2(row[16 * kkB + 2 * t],     row[16 * kkB + 2 * t + 1]);
        val.w = pk_bf2(row[16 * kkB + 2 * t + 8], row[16 * kkB + 2 * t + 9]);
        g_bfrag[(g * 2 + h) * 32 + n * 4 + t] = val;
    }
}

// ---------------------------------------------------------------------------
// Main
// ---------------------------------------------------------------------------
__global__ void __launch_bounds__(TPB, 4)
vq_main_kernel(const float* __restrict__ z,
               const float* __restrict__ cb,
               float* __restrict__ out,
               float* __restrict__ loss_out) {
    extern __shared__ __align__(16) unsigned char smem[];
    float*    s_z   = (float*)(smem + OFF_Z);
    float*    s_cn  = (float*)(smem + OFF_CN);
    float*    s_rm  = (float*)(smem + OFF_RM);
    float*    s_bst = (float*)(smem + OFF_BST);
    int*      s_bsk = (int*)(smem + OFF_BSK);
    float*    s_red = (float*)(smem + OFF_RED);
    uint32_t* s_slot= (uint32_t*)(smem + OFF_SLOT);

    const int tid  = threadIdx.x;
    const int w    = tid >> 5, lane = tid & 31;
    const int gid  = lane >> 2, tig = lane & 3;
    const int rg   = w >> 1;          // row group 0..3 (16 rows each)
    const int hc   = w & 1;           // codebook half 0/1

    // Stage cn (4/thread) + z (4 threads/vector, 16 dims each).
#pragma unroll
    for (int i = 0; i < 4; i++) s_cn[tid + i * TPB] = g_cnorm[tid + i * TPB];
    {
        int vz = tid >> 2, q = tid & 3;
        int nz = blockIdx.x * VPB + vz;
        const float* zsrc = z + ((size_t)(nz >> 10) << 16) + (nz & (HW - 1));
        float* zdst = s_z + vz * ZPAD;
#pragma unroll
        for (int i = 0; i < 16; i++) {
            int c = q * 16 + i;
            zdst[c] = zsrc[(size_t)c << 10];
        }
    }
    __syncthreads();

    // Rows: rA = rg*16+gid, rB = rA+8.
    const int rA = rg * 16 + gid;
    const int rB = rA + 8;
    const float* zrA = s_z + rA * ZPAD;
    const float* zrB = s_z + rB * ZPAD;

    // A fragments (validated mapping), values -2z in bf16.
    uint32_t afr[4][4];
#pragma unroll
    for (int kk = 0; kk < 4; kk++) {
        int c0 = 16 * kk + 2 * tig;
        afr[kk][0] = pk_bf2(-2.0f * zrA[c0],     -2.0f * zrA[c0 + 1]);
        afr[kk][1] = pk_bf2(-2.0f * zrB[c0],     -2.0f * zrB[c0 + 1]);
        afr[kk][2] = pk_bf2(-2.0f * zrA[c0 + 8], -2.0f * zrA[c0 + 9]);
        afr[kk][3] = pk_bf2(-2.0f * zrB[c0 + 8], -2.0f * zrB[c0 + 9]);
    }

    const int gbase = hc * 64;        // this warp's 64 groups (512 codes)
    uint32_t* myslot = s_slot + tid;  // strided: [slot*TPB + tid], no conflicts

    // --------- SINGLE sweep: running-threshold candidate capture ----------
    // Superset proof: lane running min >= lane final min >= row final min,
    // so s < final_th  =>  s < lane_runmin + EPS2 (always flagged).
    float rmA = INF, rmB = INF;
    float thrA = INF, thrB = INF;
    int cntA = 0, cntB = 0;
#pragma unroll 2
    for (int gg = 0; gg < 64; gg++) {
        int g = gbase + gg;
        uint4 p0 = __ldg(&g_bfrag[(g * 2 + 0) * 32 + lane]);
        uint4 p1 = __ldg(&g_bfrag[(g * 2 + 1) * 32 + lane]);
        float d[4] = {0.f, 0.f, 0.f, 0.f};
        mma_bf16(d, afr[0], p0.x, p0.y);
        mma_bf16(d, afr[1], p0.z, p0.w);
        mma_bf16(d, afr[2], p1.x, p1.y);
        mma_bf16(d, afr[3], p1.z, p1.w);
        int kb = g * 8 + 2 * tig;
        if (d[0] < thrA) {                     // rare after warm-up
            if (cntA < NSLOT) myslot[cntA * TPB] = pack_cand(d[0], kb + 0);
            cntA++;
            if (d[0] < rmA) { rmA = d[0]; thrA = rmA + EPS2; }
        }
        if (d[1] < thrA) {
            if (cntA < NSLOT) myslot[cntA * TPB] = pack_cand(d[1], kb + 1);
            cntA++;
            if (d[1] < rmA) { rmA = d[1]; thrA = rmA + EPS2; }
        }
        if (d[2] < thrB) {
            if (cntB < NSLOT) myslot[(NSLOT + cntB) * TPB] = pack_cand(d[2], kb + 0);
            cntB++;
            if (d[2] < rmB) { rmB = d[2]; thrB = rmB + EPS2; }
        }
        if (d[3] < thrB) {
            if (cntB < NSLOT) myslot[(NSLOT + cntB) * TPB] = pack_cand(d[3], kb + 1);
            cntB++;
            if (d[3] < rmB) { rmB = d[3]; thrB = rmB + EPS2; }
        }
    }
    // Merge row minima across the 4 tig lanes.
#pragma unroll
    for (int dlt = 1; dlt < 4; dlt <<= 1) {
        rmA = fminf(rmA, __shfl_xor_sync(0xFFFFFFFFu, rmA, dlt));
        rmB = fminf(rmB, __shfl_xor_sync(0xFFFFFFFFu, rmB, dlt));
    }
    if (tig == 0) {
        s_rm[rA * 2 + hc] = rmA;
        s_rm[rB * 2 + hc] = rmB;
    }
    __syncthreads();
    // FINAL per-row thresholds (min over both halves).
    const float thA = fminf(s_rm[rA * 2], s_rm[rA * 2 + 1]) + EPS2;
    const float thB = fminf(s_rm[rB * 2], s_rm[rB * 2 + 1]) + EPS2;
    const uint32_t suA = quant_th(thA), suB = quant_th(thB);

    // zn per row (reference sequential order; same smem bits both halves).
    float znA = 0.f, znB = 0.f;
#pragma unroll
    for (int c = 0; c < DIM; c++) znA = fmaf(zrA[c], zrA[c], znA);
#pragma unroll
    for (int c = 0; c < DIM; c++) znB = fmaf(zrB[c], zrB[c], znB);

    // --------- Filter slots vs FINAL threshold; exact-rescore survivors ---
    float bA = INF, bB = INF;
    int   kA = 0x7FFFFFFF, kB = 0x7FFFFFFF;
    if (cntA <= NSLOT) {
        for (int i = 0; i < cntA; i++) {
            uint32_t v = myslot[i * TPB];
            if ((v >> 16) <= suA) {
                int k = (int)(v & 0xFFFFu);
                float x = exact_score(cb, k, zrA, znA, s_cn[k]);
                if (x < bA) { bA = x; kA = k; }
            }
        }
    } else {   // overflow fallback (P ~ 1e-4): exact scan of own columns
        for (int gg = 0; gg < 64; gg++) {
            int kb = (gbase + gg) * 8 + 2 * tig;
            float x = exact_score(cb, kb, zrA, znA, s_cn[kb]);
            if (x < bA) { bA = x; kA = kb; }
            x = exact_score(cb, kb + 1, zrA, znA, s_cn[kb + 1]);
            if (x < bA) { bA = x; kA = kb + 1; }
        }
    }
    if (cntB <= NSLOT) {
        for (int i = 0; i < cntB; i++) {
            uint32_t v = myslot[(NSLOT + i) * TPB];
            if ((v >> 16) <= suB) {
                int k = (int)(v & 0xFFFFu);
                float x = exact_score(cb, k, zrB, znB, s_cn[k]);
                if (x < bB) { bB = x; kB = k; }
            }
        }
    } else {
        for (int gg = 0; gg < 64; gg++) {
            int kb = (gbase + gg) * 8 + 2 * tig;
            float x = exact_score(cb, kb, zrB, znB, s_cn[kb]);
            if (x < bB) { bB = x; kB = kb; }
            x = exact_score(cb, kb + 1, zrB, znB, s_cn[kb + 1]);
            if (x < bB) { bB = x; kB = kb + 1; }
        }
    }
    __syncwarp();

    // Merge across the 4 tig lanes; exact ties -> smaller k.
#pragma unroll
    for (int dlt = 1; dlt < 4; dlt <<= 1) {
        float ob; int ok;
        ob = __shfl_xor_sync(0xFFFFFFFFu, bA, dlt);
        ok = __shfl_xor_sync(0xFFFFFFFFu, kA, dlt);
        if (ob < bA || (ob == bA && ok < kA)) { bA = ob; kA = ok; }
        ob = __shfl_xor_sync(0xFFFFFFFFu, bB, dlt);
        ok = __shfl_xor_sync(0xFFFFFFFFu, kB, dlt);
        if (ob < bB || (ob == bB && ok < kB)) { bB = ob; kB = ok; }
    }
    if (tig == 0) {
        s_bst[rA * 2 + hc] = bA;  s_bsk[rA * 2 + hc] = kA;
        s_bst[rB * 2 + hc] = bB;  s_bsk[rB * 2 + hc] = kB;
    }
    __syncthreads();

    // Epilogue: 4 threads/vector, 16 dims each. Merge the two code-halves
    // (zn bits identical in both halves; ties -> smaller k = first index).
    const int vz = tid >> 2, q = tid & 3;
    const int nv = blockIdx.x * VPB + vz;
    float b0 = s_bst[vz * 2],  b1 = s_bst[vz * 2 + 1];
    int   h0 = s_bsk[vz * 2],  h1 = s_bsk[vz * 2 + 1];
    int bk = (b1 < b0 || (b1 == b0 && h1 < h0)) ? h1 : h0;
    if ((unsigned)bk >= NUM_CODES) bk = 0;   // defensive: never OOB
    const float* crow = cb + (size_t)bk * DIM;
    const float* zrow = s_z + vz * ZPAD;
    float* op = out + ((size_t)(nv >> 10) << 16) + (nv & (HW - 1));
    float lsum = 0.0f;
#pragma unroll
    for (int i = 0; i < 16; i++) {
        int c = q * 16 + i;
        float qv = crow[c];
        float zv = zrow[c];
        float dd = __fsub_rn(qv, zv);
        lsum = fmaf(dd, dd, lsum);
        op[(size_t)c << 10] = __fadd_rn(zv, dd);
    }

    // Deterministic block loss reduction.
    __syncthreads();
    s_red[tid] = lsum;
    __syncthreads();
#pragma unroll
    for (int st = TPB / 2; st > 0; st >>= 1) {
        if (tid < st) s_red[tid] += s_red[tid + st];
        __syncthreads();
    }
    if (tid == 0) g_partial[blockIdx.x] = s_red[0];

    // Fused finale: last CTA reduces all 512 partials in fixed order.
    if (loss_out) {
        __shared__ unsigned int s_rank;
        if (tid == 0) {
            __threadfence();
            s_rank = atomicAdd(&g_done, 1u);
        }
        __syncthreads();
        if (s_rank == NBLOCKS - 1) {
            __threadfence();
            s_red[tid] = g_partial[tid] + g_partial[tid + 256];
            __syncthreads();
#pragma unroll
            for (int st = 128; st > 0; st >>= 1) {
                if (tid < st) s_red[tid] += s_red[tid + st];
                __syncthreads();
            }
            if (tid == 0) {
                loss_out[0] = s_red[0] * (1.25f / (float)N_TOTAL);
                g_done = 0;   // reset for graph replay
            }
        }
    }
}

// ---------------------------------------------------------------------------
extern "C" void kernel_launch(void* const* d_in, const int* in_sizes, int n_in,
                              void* d_out, int out_size) {
    const float* z  = (const float*)d_in[0];
    const float* cb = (const float*)d_in[1];
    float* out = (float*)d_out;
    float* loss_out = (out_size > N_TOTAL) ? (out + (out_size - 1)) : nullptr;

    cudaFuncSetAttribute(vq_main_kernel,
                         cudaFuncAttributeMaxDynamicSharedMemorySize, SMEM_TOTAL);

    prep_kernel<<<NUM_CODES / 8, 256>>>(cb);
    vq_main_kernel<<<NBLOCKS, TPB, SMEM_TOTAL>>>(z, cb, out, loss_out);
}